// round 10
// baseline (speedup 1.0000x reference)
#include <cuda_runtime.h>
#include <math.h>

// NUFFT layer — fully analytic (round-8 math). Round-10: MUFU elimination.
// Round-9 duration was exactly explained by MUFU throughput (9.2K MUFU/SM x
// 2 cyc = 9.8us). Now: ONE __sincosf per particle (z = e^{2*pi*i*x}); all
// bases/steps derived by complex FMA (squarings + binary exponentiation).
//   step stage: z, z8=z^8 -> smem + g_step (reused by output phase)
//   phase A:    chunk bases z^{8c} via binexp, base *= z8 marching, 15-shfl
//               halving reduction per 8-mode chunk (proven round-7 code)
//   barrier;    reduce 32 partials/mode, U/V tables, edge field,
//               output: 4 thr/particle, bases z^{28q} via FMA, wrap fixes.

#define NMODES 112          // modes >= 106 underflow to exactly 0 (as reference fp32)
#define NBATCH 8
#define NPART  1024
#define GRIDB  128
#define TPB    256

__device__ float4   g_step[NBATCH * NPART];           // (zr, zi, z8r, z8i)
__device__ float    g_part[NBATCH][2 * NMODES][32];   // [b][A|B x mode][group]
__device__ unsigned g_ctr[1];

#define TWO_PI_F 6.2831853071795864769f

// complex helpers (FMA forms)
#define CMUL(rr, ri, ar, ai, br, bi) \
    do { rr = fmaf((ar), (br), -(ai) * (bi)); ri = fmaf((ar), (bi), (ai) * (br)); } while (0)
#define CSQ(rr, ri, ar, ai) \
    do { rr = fmaf((ar), (ar), -(ai) * (ai)); ri = 2.f * (ar) * (ai); } while (0)

__device__ __forceinline__ void grid_barrier()
{
    __syncthreads();
    if (threadIdx.x == 0) {
        __threadfence();
        unsigned v   = atomicAdd(&g_ctr[0], 1u);
        unsigned tgt = v - (v % GRIDB) + GRIDB;   // end of this replay's wave
        unsigned cur;
        do {
            asm volatile("ld.acquire.gpu.u32 %0, [%1];"
                         : "=r"(cur) : "l"(&g_ctr[0]) : "memory");
        } while ((int)(cur - tgt) < 0);
    }
    __syncthreads();
}

__global__ __launch_bounds__(TPB, 1) void k_fused(
    const float* __restrict__ x,
    const float* __restrict__ sigma_var,
    const float* __restrict__ shift0,
    const float* __restrict__ shift1,
    const float* __restrict__ amp0,
    const float* __restrict__ amp1,
    float* __restrict__ out)
{
    const int bb   = blockIdx.x;
    const int tid  = threadIdx.x;
    const int w    = tid >> 5;
    const int lane = tid & 31;

    __shared__ float4 sstep[64];          // block's 64 particles: (z, z8)
    __shared__ float  rowsum[2 * NMODES];
    __shared__ float4 tabU[NMODES];       // (A, B, U0, U1)
    __shared__ float2 tabV[NMODES];       // (V0, V1)  with-deconv (edge f)
    __shared__ float  sf0[12], sf1[12];   // f at grid pts {0..5, 1995..2000}

    // ---- step stage: the ONLY per-particle sincos --------------------------
    // Block bb owns particle-warps pw = 2bb, 2bb+1 (64 particles).
    if (tid < 64) {
        const int pw = 2 * bb + (tid >> 5);
        const int p  = (pw >> 5) * NPART + (pw & 31) * 32 + lane;
        const float xv = x[p];
        float zr, zi;
        __sincosf(TWO_PI_F * (xv - rintf(xv)), &zi, &zr);
        float z2r, z2i, z4r, z4i, z8r, z8i;
        CSQ(z2r, z2i, zr,  zi);
        CSQ(z4r, z4i, z2r, z2i);
        CSQ(z8r, z8i, z4r, z4i);
        float4 st = make_float4(zr, zi, z8r, z8i);
        sstep[tid] = st;
        g_step[p]  = st;                  // reused by the output phase
    }
    __syncthreads();

    // ---- Phase A: mode partials, zero sincos -------------------------------
    // Warp w: particle-half h = w>>2, quarter = w&3 (chunks {0-3|4-6|7-10|11-13}).
    {
        const int quarter = w & 3;
        const int h       = w >> 2;
        const int pw      = 2 * bb + h;
        const int b       = pw >> 5;
        const int g32     = pw & 31;

        float4 st = sstep[h * 32 + lane];
        const float zr = st.x, zi = st.y, z8r = st.z, z8i = st.w;
        float z16r, z16i, z32r, z32i, z64r, z64i;
        CSQ(z16r, z16i, z8r,  z8i);
        CSQ(z32r, z32i, z16r, z16i);
        CSQ(z64r, z64i, z32r, z32i);

        float br_, bi_;                   // base = z^{8*qs}
        int qs, qn;
        if (quarter == 0)      { br_ = 1.f;  bi_ = 0.f;  qs = 0;  qn = 4; }
        else if (quarter == 1) { br_ = z32r; bi_ = z32i; qs = 4;  qn = 3; }
        else if (quarter == 2) {              // z^56 = z32*z16*z8
            float tr, ti; CMUL(tr, ti, z32r, z32i, z16r, z16i);
            CMUL(br_, bi_, tr, ti, z8r, z8i); qs = 7;  qn = 4;
        } else {                              // z^88 = z64*z16*z8
            float tr, ti; CMUL(tr, ti, z64r, z64i, z16r, z16i);
            CMUL(br_, bi_, tr, ti, z8r, z8i); qs = 11; qn = 3;
        }

        for (int c = 0; c < qn; ++c) {    // warp-uniform bound
            const int chunk = qs + c;
            float v[16];
            float cr = br_, ci = bi_;
#pragma unroll
            for (int j = 0; j < 8; ++j) {
                v[2 * j]     = cr;
                v[2 * j + 1] = ci;
                float nr = fmaf(cr, zr, -ci * zi);
                float ni = fmaf(ci, zr,  cr * zi);
                cr = nr; ci = ni;
            }
#pragma unroll
            for (int s = 0; s < 4; ++s) { // 15-shfl halving reduction
                const int  half = 8 >> s;
                const bool up   = (lane >> s) & 1;
#pragma unroll
                for (int k = 0; k < half; ++k) {
                    float send = up ? v[k] : v[k + half];
                    float recv = __shfl_xor_sync(0xffffffffu, send, 1 << s);
                    v[k] = (up ? v[k + half] : v[k]) + recv;
                }
            }
            v[0] += __shfl_xor_sync(0xffffffffu, v[0], 16);
            if (lane < 16) {
                const int r = __brev(lane) >> 28;     // bitrev4
                const int m = chunk * 8 + (r >> 1);
                g_part[b][(r & 1) * NMODES + m][g32] = v[0];
            }
            float nbr, nbi;               // base *= z8
            CMUL(nbr, nbi, br_, bi_, z8r, z8i);
            br_ = nbr; bi_ = nbi;
        }
    }

    grid_barrier();

    // ================= Phase 2: reduce + tables + output ===================
    const int b2  = bb >> 4;              // batch (16 blocks per batch)
    const int sub = bb & 15;

    // reduce 32 group-partials per row
    if (tid < 2 * NMODES) {
        const float4* p4 = (const float4*)g_part[b2][tid];
        float s = 0.f;
#pragma unroll
        for (int k = 0; k < 8; ++k) {
            float4 u = p4[k];
            s += (u.x + u.y) + (u.z + u.w);
        }
        rowsum[tid] = s;
    }
    __syncthreads();

    // spectral multiplier tables
    if (tid < NMODES) {
        const int m = tid;
        const double TWO_PI_D = 6.283185307179586476925286766559;
        const double taud  = 12.0 / ((TWO_PI_D * 2001.0) * (TWO_PI_D * 2001.0));
        const float TAUF     = (float)taud;
        const float SQPIOTAU = (float)sqrt(3.14159265358979323846 / taud);
        const float s_   = sigma_var[0];
        const float q0   = 25.f * shift0[0] * shift0[0];
        const float q1   = 25.f * shift1[0] * shift1[0];
        const float FOURPI = 12.566370614359172f;
        float kk = TWO_PI_F * (float)m;
        float K2 = kk * kk;
        float fold = (m == 0) ? 1.f : 2.f;
        float base0 = fold * (-amp0[0]) * FOURPI / (K2 + q0);
        float inv  = 1.f / (K2 + q1);
        float base1 = fold * amp1[0] * FOURPI * inv * inv;
        float eg = __expf(-0.5f * s_ * s_ * K2);      // 0 for m >= ~106 (as ref)
        float eU = TWO_PI_F * eg;                     // window x deconv = 2*pi exactly
        float eV = SQPIOTAU * __expf((TAUF - 0.5f * s_ * s_) * K2);
        tabU[m] = make_float4(rowsum[m], rowsum[NMODES + m], base0 * eU, base1 * eU);
        tabV[m] = make_float2(base0 * eV, base1 * eV);
    }
    __syncthreads();

    // edge field: f (with deconv) at grid {0..5, 1995..2000}
    if (tid < 64) {
        const int e = tid >> 2;                       // 0..15 (12 used)
        const int q = tid & 3;
        const int g = (e < 6) ? e : (1995 + (e - 6));

        const float C_HI = (float)(1.0 / 2001.0);
        const float C_LO = (float)(1.0 / 2001.0 - (double)((float)(1.0 / 2001.0)));
        const float gf     = (float)g;
        const float phi_hi = gf * C_HI;
        const float phi_lo = fmaf(gf, C_HI, -phi_hi) + gf * C_LO;

        float sw_, cw_;
        __sincosf(TWO_PI_F * ((phi_hi - rintf(phi_hi)) + phi_lo), &sw_, &cw_);
        float zr, zi;
        if (q == 0) { zr = 1.f; zi = 0.f; }
        else {
            float m0f = (float)(28 * q);
            float hi2 = m0f * phi_hi;
            float lo2 = fmaf(m0f, phi_hi, -hi2);
            float f   = (hi2 - rintf(hi2)) + (lo2 + m0f * phi_lo);
            __sincosf(TWO_PI_F * (f - rintf(f)), &zi, &zr);
        }
        float acc0 = 0.f, acc1 = 0.f;
#pragma unroll
        for (int j = 0; j < 28; ++j) {
            const int m = 28 * q + j;
            float4 t4 = tabU[m];                      // A, B
            float2 v2 = tabV[m];                      // V0, V1
            float tt = fmaf(t4.x, zr, t4.y * zi);
            acc0 = fmaf(v2.x, tt, acc0);
            acc1 = fmaf(v2.y, tt, acc1);
            float nzr = fmaf(zr, cw_, -zi * sw_);
            float nzi = fmaf(zi, cw_,  zr * sw_);
            zr = nzr; zi = nzi;
        }
        acc0 += __shfl_xor_sync(0xffffffffu, acc0, 1);
        acc0 += __shfl_xor_sync(0xffffffffu, acc0, 2);
        acc1 += __shfl_xor_sync(0xffffffffu, acc1, 1);
        acc1 += __shfl_xor_sync(0xffffffffu, acc1, 2);
        if (q == 0 && e < 12) { sf0[e] = acc0; sf1[e] = acc1; }
    }
    __syncthreads();

    // output: 4 threads/particle, bases z^{28q} via FMA (zero sincos)
    {
        const int s  = tid >> 2;                      // 0..63
        const int q  = tid & 3;
        const int p  = b2 * NPART + sub * 64 + s;

        float4 st = g_step[p];                        // (z, z8), written pre-barrier
        const float zr = st.x, zi = st.y, z8r = st.z, z8i = st.w;

        // z28 = z16 * z8 * z4
        float z2r, z2i, z4r, z4i, z16r, z16i, tr, ti, z28r, z28i;
        CSQ(z2r, z2i, zr, zi);
        CSQ(z4r, z4i, z2r, z2i);
        CSQ(z16r, z16i, z8r, z8i);
        CMUL(tr, ti, z16r, z16i, z8r, z8i);
        CMUL(z28r, z28i, tr, ti, z4r, z4i);
        // base = z28^q via bit decomposition
        float t2r, t2i;  CSQ(t2r, t2i, z28r, z28i);   // z56
        float b1r = (q & 1) ? z28r : 1.f, b1i = (q & 1) ? z28i : 0.f;
        float b2r = (q & 2) ? t2r  : 1.f, b2i = (q & 2) ? t2i  : 0.f;
        float cr, ci;
        CMUL(cr, ci, b1r, b1i, b2r, b2i);

        float acc0 = 0.f, acc1 = 0.f;
#pragma unroll
        for (int j = 0; j < 28; ++j) {
            float4 t4 = tabU[28 * q + j];
            float tt = fmaf(t4.x, cr, t4.y * ci);
            acc0 = fmaf(t4.z, tt, acc0);
            acc1 = fmaf(t4.w, tt, acc1);
            float nr = fmaf(cr, zr, -ci * zi);
            float ni = fmaf(ci, zr,  cr * zi);
            cr = nr; ci = ni;
        }
        acc0 += __shfl_xor_sync(0xffffffffu, acc0, 1);
        acc0 += __shfl_xor_sync(0xffffffffu, acc0, 2);
        acc1 += __shfl_xor_sync(0xffffffffu, acc1, 1);
        acc1 += __shfl_xor_sync(0xffffffffu, acc1, 2);

        if (q == 0) {
            const float xv = x[p];
            // wrap corrections (reference clamps; Poisson periodizes)
            const double TWO_PI_D = 6.283185307179586476925286766559;
            const float TAUF    = (float)(12.0 / ((TWO_PI_D * 2001.0) * (TWO_PI_D * 2001.0)));
            const float inv4tau = 1.f / (4.f * TAUF);
            const float invN    = (float)(1.0 / 2001.0);
            const int m0 = __float2int_rn(xv * 2001.0f);
            if (m0 <= 6) {
#pragma unroll
                for (int j = 1; j <= 6; ++j) {        // phantom n = -j -> grid 2001-j
                    float d = xv + (float)j * invN;
                    float wgt = invN * __expf(-d * d * inv4tau);
                    acc0 -= wgt * sf0[12 - j];
                    acc1 -= wgt * sf1[12 - j];
                }
            }
            if (m0 >= 1994) {
#pragma unroll
                for (int j = 0; j <= 5; ++j) {        // phantom n = 2001+j -> grid j
                    float d = xv - 1.f - (float)j * invN;
                    float wgt = invN * __expf(-d * d * inv4tau);
                    acc0 -= wgt * sf0[j];
                    acc1 -= wgt * sf1[j];
                }
            }
            out[2 * p]     = acc0;
            out[2 * p + 1] = acc1;
        }
    }
}

// ---------------------------------------------------------------------------
extern "C" void kernel_launch(void* const* d_in, const int* in_sizes, int n_in,
                              void* d_out, int out_size)
{
    (void)in_sizes; (void)n_in; (void)out_size;
    k_fused<<<GRIDB, TPB>>>((const float*)d_in[0], (const float*)d_in[1],
                            (const float*)d_in[2], (const float*)d_in[3],
                            (const float*)d_in[4], (const float*)d_in[5],
                            (float*)d_out);
}